// round 14
// baseline (speedup 1.0000x reference)
#include <cuda_runtime.h>

#define B  32
#define NG 64
#define A  8400
#define C  80
#define TK 13
#define MAXL 1024
#define EPSF 1e-9f

typedef unsigned long long ull;

// -------- scratch (__device__ globals, zero-initialized at load) --------
__device__ ull           g_list[(size_t)B*NG*MAXL]; // compact in-gts keys per (b,j)
__device__ int           g_lcount[B*NG];            // zeroed by k_topk after use
__device__ int           g_count[B*A];              // re-init each run by k_pair
__device__ int           g_firstj[B*A];
__device__ int           g_tj[B*A];
__device__ float         g_alfg[B*A];
__device__ unsigned int  g_posalign[B*NG];          // zeroed by k_pair block 0
__device__ unsigned int  g_posov[B*NG];
__device__ int           g_wl[B*NG*TK];
__device__ int           g_wlcount;                 // zeroed by k_pair

__device__ __forceinline__ float iou_box(float4 g, float4 pb, float area2) {
    float ow = fmaxf(fminf(g.z, pb.z) - fmaxf(g.x, pb.x), 0.f);
    float oh = fmaxf(fminf(g.w, pb.w) - fmaxf(g.y, pb.y), 0.f);
    float ov = ow * oh;
    float area1 = fmaxf(g.z - g.x, 0.f) * fmaxf(g.w - g.y, 0.f);
    return ov / (area1 + area2 - ov + EPSF);
}
__device__ __forceinline__ float align_val(float sc, float iou) {
    float i2 = iou * iou;
    float i6 = i2 * i2 * i2;
    return sc * i6;
}

// K1: tile-pruned membership + sparse list append. Also re-inits per-run scratch.
__global__ void __launch_bounds__(256) k_pair(
        const float* __restrict__ pd_scores,
        const float* __restrict__ pd_bboxes,
        const float* __restrict__ anc,
        const int*   __restrict__ gl,
        const float* __restrict__ gtb) {
    int b = blockIdx.y;
    int a = blockIdx.x * 256 + threadIdx.x;
    __shared__ float4 sgt[NG];
    __shared__ int    slbl[NG];
    __shared__ ull    stile[64];       // 8x8 grid of 80px tiles -> gt mask

    if (blockIdx.x == 0 && threadIdx.x < NG) {
        g_posalign[b*NG + threadIdx.x] = 0u;
        g_posov[b*NG + threadIdx.x]    = 0u;
        if (b == 0 && threadIdx.x == 0) g_wlcount = 0;
    }
    if (threadIdx.x < NG) {
        sgt[threadIdx.x]  = reinterpret_cast<const float4*>(gtb)[b*NG + threadIdx.x];
        slbl[threadIdx.x] = gl[b*NG + threadIdx.x];
    }
    __syncthreads();
    // build conservative tile->gt masks (threads 0..63, one tile each)
    if (threadIdx.x < 64) {
        int tx = threadIdx.x & 7, ty = threadIdx.x >> 3;
        float x0 = tx * 80.f, x1 = x0 + 80.f;
        float y0 = ty * 80.f, y1 = y0 + 80.f;
        ull m = 0ull;
        #pragma unroll
        for (int j = 0; j < NG; j++) {
            float4 g = sgt[j];
            if (g.x < x1 && g.z > x0 && g.y < y1 && g.w > y0) m |= (1ull << j);
        }
        stile[threadIdx.x] = m;
    }
    __syncthreads();
    if (a >= A) return;

    int i = b*A + a;
    g_count[i] = 0; g_firstj[i] = 0x7fffffff; g_tj[i] = 0;

    float2 ap = reinterpret_cast<const float2*>(anc)[a];
    int tx = min(7, (int)(ap.x * 0.0125f));
    int ty = min(7, (int)(ap.y * 0.0125f));
    ull cand = stile[ty*8 + tx];
    if (!cand) return;

    float4 pb = reinterpret_cast<const float4*>(pd_bboxes)[(size_t)b*A + a];
    float area2 = fmaxf(pb.z - pb.x, 0.f) * fmaxf(pb.w - pb.y, 0.f);
    const float* srow = pd_scores + (size_t)i * C;
    while (cand) {
        int j = __ffsll(cand) - 1;
        cand &= cand - 1ull;
        float4 g = sgt[j];
        float mn = fminf(fminf(ap.x - g.x, ap.y - g.y),
                         fminf(g.z - ap.x, g.w - ap.y));
        if (mn > EPSF) {
            float iou = iou_box(g, pb, area2);
            float al  = align_val(__ldg(srow + slbl[j]), iou);
            ull key = ((ull)(__float_as_uint(al) | 0x80000000u) << 32) |
                      (ull)(~(unsigned)a);
            int slot = atomicAdd(&g_lcount[b*NG + j], 1);
            if (slot < MAXL)
                g_list[(size_t)(b*NG + j) * MAXL + slot] = key;
        }
    }
}

__device__ __forceinline__ void tk_insert_key(ull* top, ull key) {
    if (key > top[TK-1]) {
        top[TK-1] = key;
        #pragma unroll
        for (int t = TK-1; t > 0; t--) {
            if (top[t] > top[t-1]) {
                ull tmp = top[t]; top[t] = top[t-1]; top[t-1] = tmp;
            }
        }
    }
}

// 64-bit warp max via two redux.sync.max.u32
__device__ __forceinline__ ull warp_max64(ull h) {
    unsigned hi = (unsigned)(h >> 32);
    unsigned mhi = __reduce_max_sync(0xFFFFFFFFu, hi);
    unsigned lo = (hi == mhi) ? (unsigned)(h & 0xFFFFFFFFull) : 0u;
    unsigned mlo = __reduce_max_sync(0xFFFFFFFFu, lo);
    return ((ull)mhi << 32) | mlo;
}

// K2: warp-per-row exact stable top-13 (list ∪ lowest-index zero anchors)
//     + fused scatter + fg worklist. Zeroes g_lcount for the next run.
__global__ void __launch_bounds__(256) k_topk(const float* __restrict__ mask_gt) {
    int warp = threadIdx.x >> 5, lane = threadIdx.x & 31;
    int bn = blockIdx.x * 8 + warp;            // < B*NG
    __shared__ unsigned bm[8][64];
    __shared__ ull swin[8][TK];

    int cnt = min(g_lcount[bn], MAXL);
    if (lane == 0) g_lcount[bn] = 0;           // self-clean for next replay
    if (mask_gt[bn] == 0.f) return;

    const ull* __restrict__ list = g_list + (size_t)bn * MAXL;

    bm[warp][lane] = 0u; bm[warp][lane + 32] = 0u;
    __syncwarp();

    ull top[TK];
    #pragma unroll
    for (int t = 0; t < TK; t++) top[t] = 0ull;

    for (int i = lane; i < cnt; i += 32) {
        ull k = list[i];
        unsigned idx = ~(unsigned)(k & 0xFFFFFFFFull);
        if (idx < 2048) atomicOr(&bm[warp][idx >> 5], 1u << (idx & 31));
        tk_insert_key(top, k);
    }
    __syncwarp();

    // lane 0: 13 smallest NON-in-gts indices as explicit zero-value candidates
    if (lane == 0) {
        int found = 0;
        for (int w = 0; w < 64 && found < TK; w++) {
            unsigned z = ~bm[warp][w];
            while (z && found < TK) {
                int bit = __ffs(z) - 1; z &= z - 1u;
                unsigned idx = (unsigned)(w*32 + bit);
                tk_insert_key(top, (0x80000000ull << 32) | (ull)(~idx));
                found++;
            }
        }
    }
    __syncwarp();

    // 13 rounds of warp argmax + pop (keys unique)
    ull h = top[0];
    for (int r = 0; r < TK; r++) {
        ull m = warp_max64(h);
        if (lane == 0) swin[warp][r] = m;
        if (h == m) {
            #pragma unroll
            for (int t = 0; t < TK-1; t++) top[t] = top[t+1];
            top[TK-1] = 0ull;
            h = top[0];
        }
    }
    __syncwarp();

    // membership flags for zero-valued winners (in-gts iff key present in list)
    unsigned flags = 0u;
    for (int i = lane; i < cnt; i += 32) {
        ull k = list[i];
        #pragma unroll
        for (int t = 0; t < TK; t++) if (k == swin[warp][t]) flags |= (1u << t);
    }
    flags = __reduce_or_sync(0xFFFFFFFFu, flags);

    if (lane < TK) {
        ull k = swin[warp][lane];
        unsigned hi = (unsigned)(k >> 32);
        if (hi > 0x80000000u || (flags >> lane & 1u)) {
            unsigned a = ~(unsigned)(k & 0xFFFFFFFFull);
            int b = bn >> 6, j = bn & (NG-1);
            int old = atomicAdd(&g_count[b*A + a], 1);
            atomicMin(&g_firstj[b*A + a], j);
            if (old == 0) {
                int w = atomicAdd(&g_wlcount, 1);
                g_wl[w] = b*A + (int)a;
            }
        }
    }
}

// K3: sparse resolve over fg worklist only.
__global__ void __launch_bounds__(256) k_resolve(
        const float* __restrict__ pd_scores,
        const float* __restrict__ pd_bboxes,
        const float* __restrict__ gtb,
        const int*   __restrict__ gl) {
    int idx = blockIdx.x * 256 + threadIdx.x;
    if (idx >= g_wlcount) return;
    int e = g_wl[idx];
    int b = e / A;

    float4 pb = reinterpret_cast<const float4*>(pd_bboxes)[(size_t)e];
    float area2 = fmaxf(pb.z - pb.x, 0.f) * fmaxf(pb.w - pb.y, 0.f);
    const float4* gbox = reinterpret_cast<const float4*>(gtb) + b*NG;

    int c = g_count[e];
    int tj;
    float ov_tj;
    if (c == 1) {
        tj = g_firstj[e];
        ov_tj = iou_box(__ldg(gbox + tj), pb, area2);
    } else {
        tj = 0; ov_tj = -1.f;
        #pragma unroll 4
        for (int j = 0; j < NG; j++) {          // argmax over overlaps, first max wins
            float v = iou_box(__ldg(gbox + j), pb, area2);
            if (v > ov_tj) { ov_tj = v; tj = j; }
        }
    }
    float sc = __ldg(pd_scores + (size_t)e * C + __ldg(gl + b*NG + tj));
    float al = align_val(sc, ov_tj);
    g_tj[e]   = tj;
    g_alfg[e] = al;
    atomicMax(&g_posalign[b*NG + tj], __float_as_uint(al));
    atomicMax(&g_posov[b*NG + tj],    __float_as_uint(ov_tj));
}

// K4: emit (labels, bboxes, scores, fg); coalesced one-hot score writes.
__global__ void __launch_bounds__(256) k_output(
        const int*   __restrict__ gl,
        const float* __restrict__ gtb,
        float* __restrict__ out) {
    int b  = blockIdx.y;
    int a0 = blockIdx.x * 256;
    int a  = a0 + threadIdx.x;

    __shared__ float4 sgt[NG];
    __shared__ int    slbl[NG];
    __shared__ float  spa[NG], spo[NG];
    __shared__ int    alb[256];
    __shared__ float  asv[256];

    if (threadIdx.x < NG) {
        sgt[threadIdx.x]  = reinterpret_cast<const float4*>(gtb)[b*NG + threadIdx.x];
        int l = gl[b*NG + threadIdx.x];
        slbl[threadIdx.x] = (l < 0) ? 0 : l;
        spa[threadIdx.x] = __uint_as_float(g_posalign[b*NG + threadIdx.x]);
        spo[threadIdx.x] = __uint_as_float(g_posov[b*NG + threadIdx.x]);
    }
    __syncthreads();

    float* o_lbl = out;
    float* o_bb  = out + (size_t)B*A;
    float* o_sc  = out + (size_t)B*A*5;
    float* o_fg  = out + (size_t)B*A*85;

    if (a < A) {
        int i = b*A + a;
        int fg = (g_count[i] > 0);
        int tj = g_tj[i];
        int lbl = slbl[tj];
        float norm = 0.f;
        if (fg) norm = g_alfg[i] * spo[tj] / (spa[tj] + EPSF);
        alb[threadIdx.x] = lbl;
        asv[threadIdx.x] = fg ? norm : 0.f;
        o_lbl[i] = (float)lbl;
        reinterpret_cast<float4*>(o_bb)[i] = sgt[tj];
        o_fg[i]  = fg ? 1.f : 0.f;
    }
    __syncthreads();

    int nrows = min(256, A - a0);
    float4* dst = reinterpret_cast<float4*>(o_sc) + ((size_t)b*A + a0) * 20;
    for (int idx = threadIdx.x; idx < nrows*20; idx += 256) {
        int r  = idx / 20;
        int c4 = idx % 20;
        int lbl = alb[r];
        float4 v = make_float4(0.f, 0.f, 0.f, 0.f);
        int base = c4 * 4;
        if (lbl >= base && lbl < base + 4) (&v.x)[lbl - base] = asv[r];
        dst[idx] = v;
    }
}

extern "C" void kernel_launch(void* const* d_in, const int* in_sizes, int n_in,
                              void* d_out, int out_size) {
    const float* pd_scores = (const float*)d_in[0];
    const float* pd_bboxes = (const float*)d_in[1];
    const float* anc       = (const float*)d_in[2];
    const int*   gl        = (const int*)  d_in[3];
    const float* gtb       = (const float*)d_in[4];
    const float* mask_gt   = (const float*)d_in[5];
    float* out = (float*)d_out;

    dim3 ga((A + 255)/256, B);
    k_pair<<<ga, 256>>>(pd_scores, pd_bboxes, anc, gl, gtb);
    k_topk<<<B*NG/8, 256>>>(mask_gt);
    k_resolve<<<(B*NG*TK + 255)/256, 256>>>(pd_scores, pd_bboxes, gtb, gl);
    k_output<<<ga, 256>>>(gl, gtb, out);
}

// round 16
// speedup vs baseline: 1.0067x; 1.0067x over previous
#include <cuda_runtime.h>

#define B  32
#define NG 64
#define A  8400
#define C  80
#define TK 13
#define MAXL 1024
#define EPSF 1e-9f

typedef unsigned long long ull;

// -------- scratch (__device__ globals, zero-initialized at load) --------
__device__ ull           g_list[(size_t)B*NG*MAXL]; // compact in-gts keys per (b,j)
__device__ int           g_lcount[B*NG];            // zeroed by k_topk after use
__device__ int           g_count[B*A];              // re-init each run by k_pair
__device__ int           g_tj[B*A];                 // written only for fg anchors
__device__ float         g_alfg[B*A];               // written only for fg anchors
__device__ unsigned int  g_posalign[B*NG];          // zeroed by k_pair block 0
__device__ unsigned int  g_posov[B*NG];
__device__ int           g_wl[B*NG*TK];             // packed: (b*A+a) | (j<<19)
__device__ int           g_wlcount;                 // zeroed by k_pair

__device__ __forceinline__ float iou_box(float4 g, float4 pb, float area2) {
    float ow = fmaxf(fminf(g.z, pb.z) - fmaxf(g.x, pb.x), 0.f);
    float oh = fmaxf(fminf(g.w, pb.w) - fmaxf(g.y, pb.y), 0.f);
    float ov = ow * oh;
    float area1 = fmaxf(g.z - g.x, 0.f) * fmaxf(g.w - g.y, 0.f);
    return ov / (area1 + area2 - ov + EPSF);
}
__device__ __forceinline__ float align_val(float sc, float iou) {
    float i2 = iou * iou;
    float i6 = i2 * i2 * i2;
    return sc * i6;
}

// K1: tile-pruned membership + sparse list append. Re-inits per-run scratch.
__global__ void __launch_bounds__(256) k_pair(
        const float* __restrict__ pd_scores,
        const float* __restrict__ pd_bboxes,
        const float* __restrict__ anc,
        const int*   __restrict__ gl,
        const float* __restrict__ gtb) {
    int b = blockIdx.y;
    int a = blockIdx.x * 256 + threadIdx.x;
    __shared__ float4 sgt[NG];
    __shared__ int    slbl[NG];
    __shared__ ull    stile[64];       // 8x8 grid of 80px tiles -> gt mask

    if (blockIdx.x == 0 && threadIdx.x < NG) {
        g_posalign[b*NG + threadIdx.x] = 0u;
        g_posov[b*NG + threadIdx.x]    = 0u;
        if (b == 0 && threadIdx.x == 0) g_wlcount = 0;
    }
    if (threadIdx.x < NG) {
        sgt[threadIdx.x]  = reinterpret_cast<const float4*>(gtb)[b*NG + threadIdx.x];
        slbl[threadIdx.x] = gl[b*NG + threadIdx.x];
    }
    __syncthreads();
    if (threadIdx.x < 64) {
        int tx = threadIdx.x & 7, ty = threadIdx.x >> 3;
        float x0 = tx * 80.f, x1 = x0 + 80.f;
        float y0 = ty * 80.f, y1 = y0 + 80.f;
        ull m = 0ull;
        #pragma unroll
        for (int j = 0; j < NG; j++) {
            float4 g = sgt[j];
            if (g.x < x1 && g.z > x0 && g.y < y1 && g.w > y0) m |= (1ull << j);
        }
        stile[threadIdx.x] = m;
    }
    __syncthreads();
    if (a >= A) return;

    int i = b*A + a;
    g_count[i] = 0;

    float2 ap = reinterpret_cast<const float2*>(anc)[a];
    int tx = min(7, (int)(ap.x * 0.0125f));
    int ty = min(7, (int)(ap.y * 0.0125f));
    ull cand = stile[ty*8 + tx];
    if (!cand) return;

    float4 pb = reinterpret_cast<const float4*>(pd_bboxes)[(size_t)b*A + a];
    float area2 = fmaxf(pb.z - pb.x, 0.f) * fmaxf(pb.w - pb.y, 0.f);
    const float* srow = pd_scores + (size_t)i * C;
    while (cand) {
        int j = __ffsll(cand) - 1;
        cand &= cand - 1ull;
        float4 g = sgt[j];
        float mn = fminf(fminf(ap.x - g.x, ap.y - g.y),
                         fminf(g.z - ap.x, g.w - ap.y));
        if (mn > EPSF) {
            float iou = iou_box(g, pb, area2);
            float al  = align_val(__ldg(srow + slbl[j]), iou);
            ull key = ((ull)(__float_as_uint(al) | 0x80000000u) << 32) |
                      (ull)(~(unsigned)a);
            int slot = atomicAdd(&g_lcount[b*NG + j], 1);
            if (slot < MAXL)
                g_list[(size_t)(b*NG + j) * MAXL + slot] = key;
        }
    }
}

__device__ __forceinline__ void tk_insert_key(ull* top, ull key) {
    if (key > top[TK-1]) {
        top[TK-1] = key;
        #pragma unroll
        for (int t = TK-1; t > 0; t--) {
            if (top[t] > top[t-1]) {
                ull tmp = top[t]; top[t] = top[t-1]; top[t-1] = tmp;
            }
        }
    }
}

__device__ __forceinline__ ull warp_max64(ull h) {
    unsigned hi = (unsigned)(h >> 32);
    unsigned mhi = __reduce_max_sync(0xFFFFFFFFu, hi);
    unsigned lo = (hi == mhi) ? (unsigned)(h & 0xFFFFFFFFull) : 0u;
    unsigned mlo = __reduce_max_sync(0xFFFFFFFFu, lo);
    return ((ull)mhi << 32) | mlo;
}

// K2: warp-per-row exact stable top-13 + fused scatter + packed fg worklist.
__global__ void __launch_bounds__(256) k_topk(const float* __restrict__ mask_gt) {
    int warp = threadIdx.x >> 5, lane = threadIdx.x & 31;
    int bn = blockIdx.x * 8 + warp;            // < B*NG
    __shared__ unsigned bm[8][64];
    __shared__ ull swin[8][TK];

    int cnt = min(g_lcount[bn], MAXL);
    if (lane == 0) g_lcount[bn] = 0;           // self-clean for next replay
    if (mask_gt[bn] == 0.f) return;

    const ull* __restrict__ list = g_list + (size_t)bn * MAXL;

    bm[warp][lane] = 0u; bm[warp][lane + 32] = 0u;
    __syncwarp();

    ull top[TK];
    #pragma unroll
    for (int t = 0; t < TK; t++) top[t] = 0ull;

    for (int i = lane; i < cnt; i += 32) {
        ull k = list[i];
        unsigned idx = ~(unsigned)(k & 0xFFFFFFFFull);
        if (idx < 2048) atomicOr(&bm[warp][idx >> 5], 1u << (idx & 31));
        tk_insert_key(top, k);
    }
    __syncwarp();

    if (lane == 0) {   // 13 smallest NON-in-gts indices as zero-value candidates
        int found = 0;
        for (int w = 0; w < 64 && found < TK; w++) {
            unsigned z = ~bm[warp][w];
            while (z && found < TK) {
                int bit = __ffs(z) - 1; z &= z - 1u;
                unsigned idx = (unsigned)(w*32 + bit);
                tk_insert_key(top, (0x80000000ull << 32) | (ull)(~idx));
                found++;
            }
        }
    }
    __syncwarp();

    ull h = top[0];
    for (int r = 0; r < TK; r++) {
        ull m = warp_max64(h);
        if (lane == 0) swin[warp][r] = m;
        if (h == m) {
            #pragma unroll
            for (int t = 0; t < TK-1; t++) top[t] = top[t+1];
            top[TK-1] = 0ull;
            h = top[0];
        }
    }
    __syncwarp();

    unsigned flags = 0u;
    for (int i = lane; i < cnt; i += 32) {
        ull k = list[i];
        #pragma unroll
        for (int t = 0; t < TK; t++) if (k == swin[warp][t]) flags |= (1u << t);
    }
    flags = __reduce_or_sync(0xFFFFFFFFu, flags);

    if (lane < TK) {
        ull k = swin[warp][lane];
        unsigned hi = (unsigned)(k >> 32);
        if (hi > 0x80000000u || (flags >> lane & 1u)) {
            unsigned a = ~(unsigned)(k & 0xFFFFFFFFull);
            int b = bn >> 6, j = bn & (NG-1);
            int e = b*A + (int)a;
            int old = atomicAdd(&g_count[e], 1);
            if (old == 0) {                     // claimer: for c==1 its j is unique
                int w = atomicAdd(&g_wlcount, 1);
                g_wl[w] = e | (j << 19);        // e < 2^19
            }
        }
    }
}

// K3: sparse resolve over packed fg worklist.
__global__ void __launch_bounds__(256) k_resolve(
        const float* __restrict__ pd_scores,
        const float* __restrict__ pd_bboxes,
        const float* __restrict__ gtb,
        const int*   __restrict__ gl) {
    int idx = blockIdx.x * 256 + threadIdx.x;
    if (idx >= g_wlcount) return;
    int wle = g_wl[idx];
    int e = wle & 0x7FFFF;
    int j0 = wle >> 19;
    int b = e / A;

    float4 pb = reinterpret_cast<const float4*>(pd_bboxes)[(size_t)e];
    float area2 = fmaxf(pb.z - pb.x, 0.f) * fmaxf(pb.w - pb.y, 0.f);
    const float4* gbox = reinterpret_cast<const float4*>(gtb) + b*NG;

    int c = g_count[e];
    int tj;
    float ov_tj;
    if (c == 1) {
        tj = j0;
        ov_tj = iou_box(__ldg(gbox + tj), pb, area2);
    } else {
        tj = 0; ov_tj = -1.f;
        #pragma unroll 4
        for (int j = 0; j < NG; j++) {          // argmax over overlaps, first max wins
            float v = iou_box(__ldg(gbox + j), pb, area2);
            if (v > ov_tj) { ov_tj = v; tj = j; }
        }
    }
    float sc = __ldg(pd_scores + (size_t)e * C + __ldg(gl + b*NG + tj));
    float al = align_val(sc, ov_tj);
    g_tj[e]   = tj;
    g_alfg[e] = al;
    atomicMax(&g_posalign[b*NG + tj], __float_as_uint(al));
    atomicMax(&g_posov[b*NG + tj],    __float_as_uint(ov_tj));
}

// K4: streaming zero-fill of scores + sparse nonzero scatter; dense small fields.
__global__ void __launch_bounds__(256) k_output(
        const int*   __restrict__ gl,
        const float* __restrict__ gtb,
        float* __restrict__ out) {
    int b  = blockIdx.y;
    int a0 = blockIdx.x * 256;
    int a  = a0 + threadIdx.x;

    __shared__ float4 sgt[NG];
    __shared__ int    slbl[NG];
    __shared__ float  spa[NG], spo[NG];

    if (threadIdx.x < NG) {
        sgt[threadIdx.x]  = reinterpret_cast<const float4*>(gtb)[b*NG + threadIdx.x];
        int l = gl[b*NG + threadIdx.x];
        slbl[threadIdx.x] = (l < 0) ? 0 : l;
        spa[threadIdx.x] = __uint_as_float(g_posalign[b*NG + threadIdx.x]);
        spo[threadIdx.x] = __uint_as_float(g_posov[b*NG + threadIdx.x]);
    }
    __syncthreads();

    float* o_lbl = out;
    float* o_bb  = out + (size_t)B*A;
    float* o_sc  = out + (size_t)B*A*5;
    float* o_fg  = out + (size_t)B*A*85;

    int   fg = 0, tj = 0, lbl = 0, i = 0;
    float norm = 0.f;
    if (a < A) {
        i  = b*A + a;
        fg = (g_count[i] > 0);
        tj = fg ? g_tj[i] : 0;
        lbl = slbl[tj];
        if (fg) norm = g_alfg[i] * spo[tj] / (spa[tj] + EPSF);
        o_lbl[i] = (float)lbl;
        reinterpret_cast<float4*>(o_bb)[i] = sgt[tj];
        o_fg[i]  = fg ? 1.f : 0.f;
    }

    // streaming zero-fill of the block's score region (coalesced float4)
    int nrows = min(256, A - a0);
    float4* dst = reinterpret_cast<float4*>(o_sc) + ((size_t)b*A + a0) * 20;
    float4 z = make_float4(0.f, 0.f, 0.f, 0.f);
    for (int idx = threadIdx.x; idx < nrows*20; idx += 256) dst[idx] = z;
    __syncthreads();

    // sparse nonzero scatter (~20k total across grid)
    if (a < A && fg) o_sc[(size_t)i * C + lbl] = norm;
}

extern "C" void kernel_launch(void* const* d_in, const int* in_sizes, int n_in,
                              void* d_out, int out_size) {
    const float* pd_scores = (const float*)d_in[0];
    const float* pd_bboxes = (const float*)d_in[1];
    const float* anc       = (const float*)d_in[2];
    const int*   gl        = (const int*)  d_in[3];
    const float* gtb       = (const float*)d_in[4];
    const float* mask_gt   = (const float*)d_in[5];
    float* out = (float*)d_out;

    dim3 ga((A + 255)/256, B);
    k_pair<<<ga, 256>>>(pd_scores, pd_bboxes, anc, gl, gtb);
    k_topk<<<B*NG/8, 256>>>(mask_gt);
    k_resolve<<<(B*NG*TK + 255)/256, 256>>>(pd_scores, pd_bboxes, gtb, gl);
    k_output<<<ga, 256>>>(gl, gtb, out);
}